// round 4
// baseline (speedup 1.0000x reference)
#include <cuda_runtime.h>
#include <math.h>
#include <stdint.h>

#define B_  8
#define S_  1024
#define D_  768
#define H_  12
#define DP_ 64

// Scratch (device globals: allocation-free per harness rules)
__device__ __align__(16) float g_qh[(size_t)B_*H_*S_*DP_];
__device__ __align__(16) float g_kh[(size_t)B_*H_*S_*DP_];
__device__ __align__(16) float g_vh[(size_t)B_*H_*S_*DP_];
__device__ __align__(16) float g_attn[(size_t)B_*S_*D_];
// R[bh*1024 + i][t] = q_i . Er[t]   (only causal band t >= 1023-i is written/read)
__device__ __align__(16) float g_R[(size_t)B_*H_*S_*S_];

typedef unsigned long long ull;

// ---------------------------------------------------------------------------
// packed f32x2 helpers
// ---------------------------------------------------------------------------
__device__ __forceinline__ void ffma2(ull& c, ull a, ull b) {
    asm("fma.rn.f32x2 %0, %1, %2, %0;" : "+l"(c) : "l"(a), "l"(b));
}
__device__ __forceinline__ ull splat2(float v) {
    ull p;
    asm("mov.b64 %0, {%1, %1};" : "=l"(p) : "f"(v));
    return p;
}
__device__ __forceinline__ float2 u2f2(ull x) {
    float2 r;
    r.x = __uint_as_float((unsigned)x);
    r.y = __uint_as_float((unsigned)(x >> 32));
    return r;
}

// ===========================================================================
// FFMA2 NT GEMM:  C[M,N] = A[M,K] @ W[N,K]^T (+ bias)
// Block 128x128, K-step 16, 256 threads, 8x8 per thread (f32x2 over n-pairs).
// A staged in smem DUPLICATED (splat pairs); B staged transposed.
// mode 0: out row-major [M, 768]      (+bias)
// mode 1: out[((b*H+h)*S+s)*64+d]     (+bias)
// mode 2: out row-major [M, 1024], no bias, causal-band early-exit (R pass)
// ===========================================================================
__global__ __launch_bounds__(256, 2) void gemm_f32x2(
    const float* __restrict__ A, const float* __restrict__ W,
    const float* __restrict__ bias, float* __restrict__ out,
    int K, int mode)
{
    __shared__ __align__(16) float As2[16 * 256];   // [kk][2*row] duplicated
    __shared__ __align__(16) float Bs [16 * 128];   // [kk][col]

    const int tid = threadIdx.x;
    const int ty  = tid >> 4;    // 0..15
    const int tx  = tid & 15;    // 0..15
    const int m0  = blockIdx.y * 128;
    const int n0  = blockIdx.x * 128;

    // R pass: skip tiles fully outside the causal band t >= 1023 - i
    if (mode == 2 && ((m0 & 1023) + n0 < S_ - 255)) return;

    ull c2[8][4];
#pragma unroll
    for (int i = 0; i < 8; i++)
#pragma unroll
        for (int j = 0; j < 4; j++) c2[i][j] = 0ull;

    for (int k0 = 0; k0 < K; k0 += 16) {
#pragma unroll
        for (int t = 0; t < 2; t++) {
            int fidx = tid + t * 256;        // 0..511
            int row  = fidx >> 2;            // 0..127
            int c4   = (fidx & 3) << 2;      // 0,4,8,12
            float4 av = *(const float4*)&A[(size_t)(m0 + row) * K + k0 + c4];
            float va[4] = {av.x, av.y, av.z, av.w};
#pragma unroll
            for (int c = 0; c < 4; c++)
                *(ull*)&As2[(c4 + c) * 256 + 2 * row] = splat2(va[c]);
            float4 wv = *(const float4*)&W[(size_t)(n0 + row) * K + k0 + c4];
            float vb[4] = {wv.x, wv.y, wv.z, wv.w};
#pragma unroll
            for (int c = 0; c < 4; c++)
                Bs[(c4 + c) * 128 + row] = vb[c];
        }
        __syncthreads();

#pragma unroll
        for (int kk = 0; kk < 16; kk++) {
            ull a2[8];
            const ulonglong2* ap = (const ulonglong2*)&As2[kk * 256 + 16 * ty];
            ulonglong2 av0 = ap[0], av1 = ap[1], av2 = ap[2], av3 = ap[3];
            a2[0] = av0.x; a2[1] = av0.y; a2[2] = av1.x; a2[3] = av1.y;
            a2[4] = av2.x; a2[5] = av2.y; a2[6] = av3.x; a2[7] = av3.y;
            ull b2[4];
            const ulonglong2* bp = (const ulonglong2*)&Bs[kk * 128 + 8 * tx];
            ulonglong2 bv0 = bp[0], bv1 = bp[1];
            b2[0] = bv0.x; b2[1] = bv0.y; b2[2] = bv1.x; b2[3] = bv1.y;
#pragma unroll
            for (int i = 0; i < 8; i++)
#pragma unroll
                for (int j = 0; j < 4; j++)
                    ffma2(c2[i][j], a2[i], b2[j]);
        }
        __syncthreads();
    }

    // Epilogue
#pragma unroll
    for (int i = 0; i < 8; i++) {
        int m  = m0 + 8 * ty + i;
        int bb = m >> 10;
        int ss = m & 1023;
#pragma unroll
        for (int jp = 0; jp < 4; jp++) {
            int n = n0 + 8 * tx + 2 * jp;
            float2 v = u2f2(c2[i][jp]);
            if (mode != 2) { v.x += bias[n]; v.y += bias[n + 1]; }
            if (mode == 1) {
                int h = n >> 6, d = n & 63;
                *(float2*)&out[(((size_t)bb * H_ + h) * S_ + ss) * DP_ + d] = v;
            } else if (mode == 0) {
                *(float2*)&out[(size_t)m * D_ + n] = v;
            } else {
                *(float2*)&out[(size_t)m * S_ + n] = v;
            }
        }
    }
}

// ---------------------------------------------------------------------------
// Fused causal attention; relative bias comes precomputed from g_R.
// logits(i,j) = 0.125 * ( q_i·k_j + R[i][1023-i+j] ),  j <= i
// grid (S/64, B*H), 256 threads, 64KB smem -> 3 CTAs/SM.
// ---------------------------------------------------------------------------
__global__ __launch_bounds__(256, 3) void attn_kernel()
{
    extern __shared__ float sm[];
    float* qs = sm;               // [64][64]  kk-major (pre-scaled by 0.125)
    float* ks = qs + 4096;        // [64][64]  kk-major
    float* vs = ks + 4096;        // [64][64]  jj-major
    float* ps = vs + 4096;        // [64][64]  jj-major (P transposed)

    const int tid = threadIdx.x;
    const int ty = tid >> 4;
    const int tx = tid & 15;
    const int i0 = blockIdx.x * 64;
    const int bh = blockIdx.y;

    const float* qp = g_qh + (size_t)bh * S_ * DP_;
    const float* kp = g_kh + (size_t)bh * S_ * DP_;
    const float* vp = g_vh + (size_t)bh * S_ * DP_;
    const float* Rp = g_R  + ((size_t)bh * S_) * S_;

    for (int idx = tid; idx < 1024; idx += 256) {
        int row = idx >> 4;
        int c4  = (idx & 15) << 2;
        float4 v = *(const float4*)&qp[(size_t)(i0 + row) * DP_ + c4];
        qs[(c4+0)*64 + row] = v.x * 0.125f;
        qs[(c4+1)*64 + row] = v.y * 0.125f;
        qs[(c4+2)*64 + row] = v.z * 0.125f;
        qs[(c4+3)*64 + row] = v.w * 0.125f;
    }

    float acc[4][4];
#pragma unroll
    for (int i = 0; i < 4; i++)
#pragma unroll
        for (int j = 0; j < 4; j++) acc[i][j] = 0.f;
    float mrow[4] = {-INFINITY, -INFINITY, -INFINITY, -INFINITY};
    float lrow[4] = {0.f, 0.f, 0.f, 0.f};

    const int ibase = i0 + 4 * ty;

    for (int j0 = 0; j0 <= i0; j0 += 64) {
        __syncthreads();   // ps/vs (prev PV) safe

        for (int idx = tid; idx < 1024; idx += 256) {
            int row = idx >> 4;
            int c4  = (idx & 15) << 2;
            float4 v = *(const float4*)&kp[(size_t)(j0 + row) * DP_ + c4];
            ks[(c4+0)*64 + row] = v.x;
            ks[(c4+1)*64 + row] = v.y;
            ks[(c4+2)*64 + row] = v.z;
            ks[(c4+3)*64 + row] = v.w;
        }
        for (int idx = tid; idx < 1024; idx += 256) {
            int row = idx >> 4;
            int c4  = (idx & 15) << 2;
            *(float4*)&vs[row*64 + c4] = *(const float4*)&vp[(size_t)(j0 + row) * DP_ + c4];
        }
        __syncthreads();

        // ---- init S from precomputed relative bias, then S += Qs @ K^T ----
        const int jbase = j0 + 4 * tx;
        float sacc[4][4];
#pragma unroll
        for (int ri = 0; ri < 4; ri++) {
            const float* Rrow = Rp + (size_t)(ibase + ri) * S_;
            int tbase = (S_ - 1) - (ibase + ri) + jbase;
#pragma unroll
            for (int ci = 0; ci < 4; ci++) {
                int t = tbase + ci;
                if (t > S_ - 1) t = S_ - 1;   // masked below; clamp to stay in-bounds
                sacc[ri][ci] = 0.125f * Rrow[t];
            }
        }

#pragma unroll 8
        for (int kk = 0; kk < 64; kk++) {
            float4 qf = *(const float4*)&qs[kk*64 + 4*ty];
            float4 kf = *(const float4*)&ks[kk*64 + 4*tx];
            float qa[4] = {qf.x, qf.y, qf.z, qf.w};
            float ka[4] = {kf.x, kf.y, kf.z, kf.w};
#pragma unroll
            for (int ri = 0; ri < 4; ri++)
#pragma unroll
                for (int ci = 0; ci < 4; ci++)
                    sacc[ri][ci] += qa[ri] * ka[ci];
        }

        if (j0 == i0) {
#pragma unroll
            for (int ri = 0; ri < 4; ri++)
#pragma unroll
                for (int ci = 0; ci < 4; ci++)
                    if (jbase + ci > ibase + ri) sacc[ri][ci] = -1e30f;
        }

#pragma unroll
        for (int ri = 0; ri < 4; ri++) {
            float mn = fmaxf(fmaxf(sacc[ri][0], sacc[ri][1]),
                             fmaxf(sacc[ri][2], sacc[ri][3]));
#pragma unroll
            for (int off = 8; off > 0; off >>= 1)
                mn = fmaxf(mn, __shfl_xor_sync(0xffffffffu, mn, off));
            float mt   = fmaxf(mrow[ri], mn);
            float corr = __expf(mrow[ri] - mt);
            mrow[ri]   = mt;
            float psum = 0.f;
#pragma unroll
            for (int ci = 0; ci < 4; ci++) {
                float p = __expf(sacc[ri][ci] - mt);
                sacc[ri][ci] = p;
                psum += p;
            }
#pragma unroll
            for (int off = 8; off > 0; off >>= 1)
                psum += __shfl_xor_sync(0xffffffffu, psum, off);
            lrow[ri] = lrow[ri] * corr + psum;
#pragma unroll
            for (int ci = 0; ci < 4; ci++) acc[ri][ci] *= corr;
        }

#pragma unroll
        for (int ri = 0; ri < 4; ri++)
#pragma unroll
            for (int ci = 0; ci < 4; ci++)
                ps[(4*tx + ci)*64 + (4*ty + ri)] = sacc[ri][ci];
        __syncthreads();

#pragma unroll 8
        for (int jj = 0; jj < 64; jj++) {
            float4 pf = *(const float4*)&ps[jj*64 + 4*ty];
            float4 vf = *(const float4*)&vs[jj*64 + 4*tx];
            float pa[4] = {pf.x, pf.y, pf.z, pf.w};
            float va[4] = {vf.x, vf.y, vf.z, vf.w};
#pragma unroll
            for (int ri = 0; ri < 4; ri++)
#pragma unroll
                for (int ci = 0; ci < 4; ci++)
                    acc[ri][ci] += pa[ri] * va[ci];
        }
    }

    const int b = bh / H_;
    const int h = bh % H_;
#pragma unroll
    for (int ri = 0; ri < 4; ri++) {
        int i = i0 + 4*ty + ri;
        float inv = 1.f / lrow[ri];
#pragma unroll
        for (int ci = 0; ci < 4; ci++) {
            g_attn[((size_t)b * S_ + i) * D_ + h * DP_ + 4*tx + ci] = acc[ri][ci] * inv;
        }
    }
}

// ---------------------------------------------------------------------------
extern "C" void kernel_launch(void* const* d_in, const int* in_sizes, int n_in,
                              void* d_out, int out_size)
{
    const float* Q  = (const float*)d_in[0];
    const float* K  = (const float*)d_in[1];
    const float* V  = (const float*)d_in[2];
    const float* Wq = (const float*)d_in[4];
    const float* bq = (const float*)d_in[5];
    const float* Wk = (const float*)d_in[6];
    const float* bk = (const float*)d_in[7];
    const float* Wv = (const float*)d_in[8];
    const float* bv = (const float*)d_in[9];
    const float* Wo = (const float*)d_in[10];
    const float* bo = (const float*)d_in[11];
    const float* Er = (const float*)d_in[12];
    float* out = (float*)d_out;

    float *qh, *kh, *vh, *attn, *Rg;
    cudaGetSymbolAddress((void**)&qh,   g_qh);
    cudaGetSymbolAddress((void**)&kh,   g_kh);
    cudaGetSymbolAddress((void**)&vh,   g_vh);
    cudaGetSymbolAddress((void**)&attn, g_attn);
    cudaGetSymbolAddress((void**)&Rg,   g_R);

    dim3 pgrid(D_ / 128, (B_ * S_) / 128);        // (6, 64)
    dim3 rgrid(S_ / 128, (B_ * H_ * S_) / 128);   // (8, 768)

    // Projections (mode 1: head-split output)
    gemm_f32x2<<<pgrid, 256>>>(Q, Wq, bq, qh, D_, 1);
    gemm_f32x2<<<pgrid, 256>>>(K, Wk, bk, kh, D_, 1);
    gemm_f32x2<<<pgrid, 256>>>(V, Wv, bv, vh, D_, 1);

    // Relative-position bias GEMM: R = qh @ Er^T   (mode 2, K=64, band-skipped)
    gemm_f32x2<<<rgrid, 256>>>(qh, Er, nullptr, Rg, DP_, 2);

    const int smem_bytes = 16384 * (int)sizeof(float);   // 64 KB
    cudaFuncSetAttribute(attn_kernel,
                         cudaFuncAttributeMaxDynamicSharedMemorySize, smem_bytes);
    attn_kernel<<<dim3(S_ / 64, B_ * H_), 256, smem_bytes>>>();

    // Output projection (mode 0)
    gemm_f32x2<<<pgrid, 256>>>(attn, Wo, bo, out, D_, 0);
}